// round 1
// baseline (speedup 1.0000x reference)
#include <cuda_runtime.h>

// ---------------- problem constants ----------------
#define BB    2
#define CFEAT 128
#define HH    64
#define WW    128
#define GG    16
#define CPG   8
#define DDISP 48
#define HID   32
#define NEG   0.2f
#define EPSBN 1e-5f

#define SPA       (DDISP*HH*WW)       // 393216 per (b,channel)
#define VOL_ELEMS (BB*GG*SPA)         // 12,582,912
#define X_ELEMS   (BB*HID*SPA)        // 25,165,824

// ---------------- scratch (static device globals; no allocation) ----------------
__device__ float  g_vol [VOL_ELEMS];
__device__ float  g_buf0[X_ELEMS];
__device__ float  g_buf1[X_ELEMS];
#define NSEG 48
__device__ float  g_part[HID*NSEG*2];
__device__ float2 g_ss  [HID];          // per-channel (scale, shift) for fused BN+LReLU

// ---------------- volume build ----------------
// vol[b,g,d,h,w] = mean_c left[b,g*8+c,h,w] * right[b,g*8+c,h,w-d]  (0 if w<d)
__global__ void vol_kernel(const float* __restrict__ left,
                           const float* __restrict__ right,
                           float* __restrict__ vol)
{
    int h = blockIdx.x % HH;
    int g = (blockIdx.x / HH) % GG;
    int b = blockIdx.x / (HH*GG);
    int w = threadIdx.x;                       // 128 threads

    __shared__ float sR[CPG][WW];
    float l[CPG];
    const float* lp = left  + (((size_t)b*CFEAT + g*CPG)*HH + h)*WW + w;
    const float* rp = right + (((size_t)b*CFEAT + g*CPG)*HH + h)*WW + w;
#pragma unroll
    for (int c = 0; c < CPG; c++) {
        l[c]     = lp[(size_t)c*HH*WW];
        sR[c][w] = rp[(size_t)c*HH*WW];
    }
    __syncthreads();

    float* vp = vol + (((size_t)b*GG + g)*DDISP)*(HH*WW) + h*WW + w;
    for (int d = 0; d < DDISP; d++) {
        float s = 0.f;
        if (w >= d) {
            int ws = w - d;
#pragma unroll
            for (int c = 0; c < CPG; c++) s += l[c]*sR[c][ws];
        }
        vp[(size_t)d*HH*WW] = s * (1.0f/CPG);
    }
}

// ---------------- tiled direct conv3d (3x3x3, SAME) ----------------
// Block: 2(d) x 8(h) x 16(w) voxel tile, all 32 output channels.
// Thread: 8 couts x 4 consecutive w -> 32 accumulators.
// Input optionally passes through fused BN affine + LeakyReLU (previous layer's BN).
#define TD 2
#define TH 8
#define TW 16
#define CD 4
#define CH 10
#define CWD 18      // valid input width of tile
#define CWP 19      // padded smem stride (reduces bank conflicts)
#define CHUNK 4

template<int CIN, bool ACT>
__global__ __launch_bounds__(256)
void conv_kernel(const float* __restrict__ in,
                 const float* __restrict__ wg,   // [COUT=32][CIN][3][3][3]
                 float* __restrict__ out)
{
    __shared__ float sIn[CHUNK][CD][CH][CWP];     // 3040 f
    __shared__ float sW [CHUNK][HID][27];         // 3456 f

    const int w0 = blockIdx.x * TW;
    const int h0 = blockIdx.y * TH;
    const int bz = blockIdx.z;
    const int b  = bz / (DDISP/TD);
    const int d0 = (bz % (DDISP/TD)) * TD;
    const int tid = threadIdx.x;

    const int coutg = tid >> 6;          // 0..3  -> 8 couts each
    const int slot  = tid & 63;
    const int tdz   = slot >> 5;         // 0..1
    const int thy   = (slot >> 2) & 7;   // 0..7
    const int twx   = (slot & 3) * 4;    // 0,4,8,12
    const int cout0 = coutg * 8;

    float acc[8][4];
#pragma unroll
    for (int o = 0; o < 8; o++)
#pragma unroll
        for (int v = 0; v < 4; v++) acc[o][v] = 0.f;

    for (int c0 = 0; c0 < CIN; c0 += CHUNK) {
        __syncthreads();   // previous compute done before overwrite

        // ---- stage weights: sW[c][o][k] (compute-side reads are broadcast)
        for (int i = tid; i < CHUNK*HID*27; i += 256) {
            int c = i / (HID*27);
            int r = i % (HID*27);
            int o = r / 27;
            int k = r % 27;
            sW[c][o][k] = wg[((size_t)o*CIN + (c0 + c))*27 + k];
        }
        // ---- stage input tile, fused affine+LeakyReLU
        for (int i = tid; i < CHUNK*CD*CH*CWD; i += 256) {
            int c  = i / (CD*CH*CWD);
            int r  = i % (CD*CH*CWD);
            int dz = r / (CH*CWD);
            int r2 = r % (CH*CWD);
            int hy = r2 / CWD;
            int wx = r2 % CWD;
            int gd = d0 - 1 + dz;
            int gh = h0 - 1 + hy;
            int gw = w0 - 1 + wx;
            float val = 0.f;
            if (gd >= 0 && gd < DDISP && gh >= 0 && gh < HH && gw >= 0 && gw < WW) {
                val = in[(((size_t)b*CIN + (c0 + c))*DDISP + gd)*(HH*WW) + gh*WW + gw];
                if (ACT) {
                    float2 s = g_ss[c0 + c];
                    val = fmaf(s.x, val, s.y);
                    val = (val > 0.f) ? val : NEG*val;
                }
            }
            sIn[c][dz][hy][wx] = val;
        }
        __syncthreads();

        // ---- compute
#pragma unroll 1
        for (int c = 0; c < CHUNK; c++) {
#pragma unroll
            for (int kd = 0; kd < 3; kd++) {
#pragma unroll
                for (int kh = 0; kh < 3; kh++) {
                    float in6[6];
#pragma unroll
                    for (int v = 0; v < 6; v++)
                        in6[v] = sIn[c][tdz + kd][thy + kh][twx + v];
#pragma unroll
                    for (int kw = 0; kw < 3; kw++) {
                        const int kidx = (kd*3 + kh)*3 + kw;
                        float wr[8];
#pragma unroll
                        for (int o = 0; o < 8; o++) wr[o] = sW[c][cout0 + o][kidx];
#pragma unroll
                        for (int o = 0; o < 8; o++)
#pragma unroll
                            for (int v = 0; v < 4; v++)
                                acc[o][v] = fmaf(wr[o], in6[kw + v], acc[o][v]);
                    }
                }
            }
        }
    }

    // ---- write out (aligned float4 per cout)
    const int gd = d0 + tdz, gh = h0 + thy, gw = w0 + twx;
#pragma unroll
    for (int o = 0; o < 8; o++) {
        float4 r = make_float4(acc[o][0], acc[o][1], acc[o][2], acc[o][3]);
        *(float4*)&out[(((size_t)b*HID + cout0 + o)*DDISP + gd)*(HH*WW) + gh*WW + gw] = r;
    }
}

// ---------------- BN stats (deterministic two-pass) ----------------
__global__ __launch_bounds__(256)
void stats_kernel(const float* __restrict__ x)
{
    const int ch  = blockIdx.y;
    const int seg = blockIdx.x;
    const int perch  = BB*SPA;          // 786432
    const int perseg = perch / NSEG;    // 16384
    const int base = seg * perseg;

    float s = 0.f, sq = 0.f;
    for (int i = base + threadIdx.x; i < base + perseg; i += 256) {
        int b = i / SPA;
        int r = i - b*SPA;
        float v = x[((size_t)b*HID + ch)*SPA + r];
        s  += v;
        sq += v*v;
    }
    __shared__ float rs[256], rq[256];
    rs[threadIdx.x] = s; rq[threadIdx.x] = sq;
    __syncthreads();
    for (int st = 128; st > 0; st >>= 1) {
        if (threadIdx.x < st) {
            rs[threadIdx.x] += rs[threadIdx.x + st];
            rq[threadIdx.x] += rq[threadIdx.x + st];
        }
        __syncthreads();
    }
    if (threadIdx.x == 0) {
        g_part[(ch*NSEG + seg)*2 + 0] = rs[0];
        g_part[(ch*NSEG + seg)*2 + 1] = rq[0];
    }
}

__global__ void finalize_kernel(const float* __restrict__ gamma,
                                const float* __restrict__ beta)
{
    int ch = threadIdx.x;
    if (ch >= HID) return;
    float s = 0.f, sq = 0.f;
    for (int k = 0; k < NSEG; k++) {
        s  += g_part[(ch*NSEG + k)*2 + 0];
        sq += g_part[(ch*NSEG + k)*2 + 1];
    }
    const float N = (float)(BB*SPA);
    float mean = s / N;
    float var  = fmaxf(sq / N - mean*mean, 0.f);
    float scale = gamma[ch] * rsqrtf(var + EPSBN);
    g_ss[ch] = make_float2(scale, beta[ch] - mean*scale);
}

// ---------------- final conv (32 -> 1) with fused BN+LReLU input ----------------
__global__ __launch_bounds__(256)
void final_kernel(const float* __restrict__ x,
                  const float* __restrict__ wf,   // [1][32][3][3][3]
                  const float* __restrict__ bf,
                  float* __restrict__ out)
{
    __shared__ float  sw[HID*27];
    __shared__ float2 sss[HID];
    for (int i = threadIdx.x; i < HID*27; i += 256) sw[i] = wf[i];
    if (threadIdx.x < HID) sss[threadIdx.x] = g_ss[threadIdx.x];
    __syncthreads();

    int idx = blockIdx.x * 256 + threadIdx.x;     // over BB*SPA
    int w = idx % WW;
    int h = (idx / WW) % HH;
    int d = (idx / (WW*HH)) % DDISP;
    int b = idx / SPA;

    float acc = bf[0];
    for (int c = 0; c < HID; c++) {
        float2 s = sss[c];
        const float* xp = x + (((size_t)b*HID + c)*DDISP)*(HH*WW);
#pragma unroll
        for (int kd = 0; kd < 3; kd++) {
            int gd = d + kd - 1; if (gd < 0 || gd >= DDISP) continue;
#pragma unroll
            for (int kh = 0; kh < 3; kh++) {
                int gh = h + kh - 1; if (gh < 0 || gh >= HH) continue;
#pragma unroll
                for (int kw = 0; kw < 3; kw++) {
                    int gw = w + kw - 1; if (gw < 0 || gw >= WW) continue;
                    float v = xp[((size_t)gd*HH + gh)*WW + gw];
                    v = fmaf(s.x, v, s.y);
                    v = (v > 0.f) ? v : NEG*v;
                    acc = fmaf(sw[c*27 + (kd*3 + kh)*3 + kw], v, acc);
                }
            }
        }
    }
    out[idx] = acc;
}

// ---------------- launch ----------------
extern "C" void kernel_launch(void* const* d_in, const int* in_sizes, int n_in,
                              void* d_out, int out_size)
{
    const float* left  = (const float*)d_in[0];
    const float* right = (const float*)d_in[1];
    const float* w1 = (const float*)d_in[2];
    const float* g1 = (const float*)d_in[3];
    const float* b1 = (const float*)d_in[4];
    const float* w2 = (const float*)d_in[5];
    const float* g2 = (const float*)d_in[6];
    const float* b2 = (const float*)d_in[7];
    const float* w3 = (const float*)d_in[8];
    const float* g3 = (const float*)d_in[9];
    const float* b3 = (const float*)d_in[10];
    const float* w4 = (const float*)d_in[11];
    const float* g4 = (const float*)d_in[12];
    const float* b4 = (const float*)d_in[13];
    const float* wf = (const float*)d_in[14];
    const float* bf = (const float*)d_in[15];
    float* out = (float*)d_out;
    (void)in_sizes; (void)n_in; (void)out_size;

    float *vol, *buf0, *buf1;
    cudaGetSymbolAddress((void**)&vol,  g_vol);
    cudaGetSymbolAddress((void**)&buf0, g_buf0);
    cudaGetSymbolAddress((void**)&buf1, g_buf1);

    dim3 cgrid(WW/TW, HH/TH, BB*(DDISP/TD));   // (8, 8, 48)
    dim3 sgrid(NSEG, HID);

    vol_kernel<<<BB*GG*HH, WW>>>(left, right, vol);

    conv_kernel<GG, false><<<cgrid, 256>>>(vol, w1, buf0);
    stats_kernel<<<sgrid, 256>>>(buf0);
    finalize_kernel<<<1, 32>>>(g1, b1);

    conv_kernel<HID, true><<<cgrid, 256>>>(buf0, w2, buf1);
    stats_kernel<<<sgrid, 256>>>(buf1);
    finalize_kernel<<<1, 32>>>(g2, b2);

    conv_kernel<HID, true><<<cgrid, 256>>>(buf1, w3, buf0);
    stats_kernel<<<sgrid, 256>>>(buf0);
    finalize_kernel<<<1, 32>>>(g3, b3);

    conv_kernel<HID, true><<<cgrid, 256>>>(buf0, w4, buf1);
    stats_kernel<<<sgrid, 256>>>(buf1);
    finalize_kernel<<<1, 32>>>(g4, b4);

    final_kernel<<<(BB*SPA)/256, 256>>>(buf1, wf, bf, out);
}